// round 1
// baseline (speedup 1.0000x reference)
#include <cuda_runtime.h>
#include <cuda_bf16.h>
#include <cstdint>

// Problem constants
#define NUM_USERS 50000
#define NUM_ITEMS 100000
#define N_NODES   150000
#define NNZ_E     2000000
#define DLAT      64
#define DMINI     16
#define DTOT      80           // fused 64 + 16
#define NBATCH    1024
#define NI_PAD    100096       // 782 * 128 (GEMM n-tile padding)

// ---------------- device scratch (allowed: __device__ globals) ----------------
__device__ int   g_rowptr[N_NODES + 1];
__device__ int   g_cnt[N_NODES];          // counts, then write cursors
__device__ int   g_bsum[256];
__device__ int   g_col[NNZ_E];
__device__ float g_val[NNZ_E];
__device__ float g_x[N_NODES * DTOT];
__device__ float g_y[N_NODES * DTOT];
__device__ float g_acc[N_NODES * DTOT];
__device__ __nv_bfloat16 g_items[NI_PAD * DLAT];
__device__ __nv_bfloat16 g_users[NBATCH * DLAT];
__device__ float g_ubias[NBATCH];

// ---------------- CSR build ----------------
__global__ void k_zero_cnt() {
    int i = blockIdx.x * blockDim.x + threadIdx.x;
    if (i < N_NODES) g_cnt[i] = 0;
}

__global__ void k_hist(const int* __restrict__ rows) {
    int e = blockIdx.x * blockDim.x + threadIdx.x;
    if (e < NNZ_E) atomicAdd(&g_cnt[rows[e]], 1);
}

__global__ void k_scanA() {
    __shared__ int s[1024];
    int tid = threadIdx.x;
    int i = blockIdx.x * 1024 + tid;
    int v = (i < N_NODES) ? g_cnt[i] : 0;
    s[tid] = v;
    __syncthreads();
    #pragma unroll
    for (int off = 1; off < 1024; off <<= 1) {
        int t = (tid >= off) ? s[tid - off] : 0;
        __syncthreads();
        s[tid] += t;
        __syncthreads();
    }
    if (i < N_NODES) g_rowptr[i + 1] = s[tid];   // block-local inclusive
    if (tid == 1023) g_bsum[blockIdx.x] = s[1023];
}

__global__ void k_scanB(int nb) {
    if (threadIdx.x == 0 && blockIdx.x == 0) {
        int run = 0;
        for (int b = 0; b < nb; b++) { int t = g_bsum[b]; g_bsum[b] = run; run += t; }
    }
}

__global__ void k_scanC() {
    int i = blockIdx.x * blockDim.x + threadIdx.x;
    if (i >= N_NODES) return;
    int incl = g_rowptr[i + 1] + g_bsum[i >> 10];
    g_rowptr[i + 1] = incl;
    int c = g_cnt[i];
    g_cnt[i] = incl - c;               // row start = write cursor
    if (i == 0) g_rowptr[0] = 0;
}

__global__ void k_scatter(const int* __restrict__ rows, const int* __restrict__ cols,
                          const float* __restrict__ vals) {
    int e = blockIdx.x * blockDim.x + threadIdx.x;
    if (e >= NNZ_E) return;
    int r = rows[e];
    int pos = atomicAdd(&g_cnt[r], 1);
    g_col[pos] = cols[e];
    g_val[pos] = vals[e];
}

// ---------------- init fused 80-dim state ----------------
__global__ void k_init(const float* __restrict__ eu, const float* __restrict__ ei,
                       const float* __restrict__ mu, const float* __restrict__ mi) {
    int i = blockIdx.x * blockDim.x + threadIdx.x;
    if (i >= N_NODES * DTOT) return;
    int n = i / DTOT;
    int d = i - n * DTOT;
    float v;
    if (d < DLAT)
        v = (n < NUM_USERS) ? eu[n * DLAT + d] : ei[(n - NUM_USERS) * DLAT + d];
    else {
        int dd = d - DLAT;
        v = (n < NUM_USERS) ? mu[n * DMINI + dd] : mi[(n - NUM_USERS) * DMINI + dd];
    }
    g_x[i] = v;
    g_acc[i] = v;
}

// ---------------- CSR SpMM: warp per row, y = A x, acc += y ----------------
__global__ void k_spmm(int dir) {
    const float* __restrict__ x = dir ? g_y : g_x;
    float* __restrict__ y       = dir ? g_x : g_y;
    int w = blockIdx.x * (blockDim.x >> 5) + (threadIdx.x >> 5);
    if (w >= N_NODES) return;
    int lane = threadIdx.x & 31;
    int s = g_rowptr[w], e = g_rowptr[w + 1];
    float a0 = 0.f, a1 = 0.f, a2 = 0.f;
    for (int i = s; i < e; i++) {
        int   c = __ldg(&g_col[i]);
        float v = __ldg(&g_val[i]);
        const float* xb = x + c * DTOT;
        a0 = fmaf(v, __ldg(&xb[lane]),      a0);
        a1 = fmaf(v, __ldg(&xb[32 + lane]), a1);
        if (lane < 16) a2 = fmaf(v, __ldg(&xb[64 + lane]), a2);
    }
    int base = w * DTOT;
    y[base + lane]      = a0;  g_acc[base + lane]      += a0;
    y[base + 32 + lane] = a1;  g_acc[base + 32 + lane] += a1;
    if (lane < 16) { y[base + 64 + lane] = a2; g_acc[base + 64 + lane] += a2; }
}

// ---------------- build bf16 users/items embeddings (fold /4 + upsample) ----------------
__global__ void k_build(const int* __restrict__ users, const float* __restrict__ bias_user) {
    int idx = blockIdx.x * blockDim.x + threadIdx.x;
    const int NITEMS = NI_PAD * DLAT;
    if (idx < NITEMS) {
        int i = idx >> 6, d = idx & 63;
        float v = 0.f;
        if (i < NUM_ITEMS) {
            int node = NUM_USERS + i;
            v = 0.25f * (g_acc[node * DTOT + d] + g_acc[node * DTOT + 64 + (d >> 2)]);
        }
        g_items[idx] = __float2bfloat16(v);
    } else if (idx < NITEMS + NBATCH * DLAT) {
        int j = idx - NITEMS;
        int b = j >> 6, d = j & 63;
        int u = users[b];
        float v = 0.25f * (g_acc[u * DTOT + d] + g_acc[u * DTOT + 64 + (d >> 2)]);
        g_users[j] = __float2bfloat16(v);
        if (d == 0) g_ubias[b] = bias_user[u];
    }
}

// ---------------- rating GEMM: bf16 mma.sync + bias + sigmoid ----------------
__device__ __forceinline__ float sigf(float x) { return 1.0f / (1.0f + __expf(-x)); }

__device__ __forceinline__ void mma16816(float c[4], uint32_t a0, uint32_t a1,
                                         uint32_t a2, uint32_t a3,
                                         uint32_t b0, uint32_t b1) {
    asm volatile(
        "mma.sync.aligned.m16n8k16.row.col.f32.bf16.bf16.f32 "
        "{%0,%1,%2,%3},{%4,%5,%6,%7},{%8,%9},{%0,%1,%2,%3};\n"
        : "+f"(c[0]), "+f"(c[1]), "+f"(c[2]), "+f"(c[3])
        : "r"(a0), "r"(a1), "r"(a2), "r"(a3), "r"(b0), "r"(b1));
}

__global__ void k_gemm(const float* __restrict__ bias_item, float* __restrict__ out) {
    int warp = threadIdx.x >> 5, lane = threadIdx.x & 31;
    int gid = lane >> 2, tg = lane & 3;
    int m0 = blockIdx.y * 64 + (warp >> 1) * 16;   // 4 m-warps
    int n0 = blockIdx.x * 128 + (warp & 1) * 64;   // 2 n-warps

    float c[8][4];
    #pragma unroll
    for (int nf = 0; nf < 8; nf++)
        #pragma unroll
        for (int q = 0; q < 4; q++) c[nf][q] = 0.f;

    int r0 = m0 + gid, r1 = r0 + 8;
    const __nv_bfloat16* U = g_users;
    const __nv_bfloat16* I = g_items;

    #pragma unroll
    for (int ks = 0; ks < DLAT; ks += 16) {
        uint32_t a0 = *(const uint32_t*)&U[r0 * DLAT + ks + tg * 2];
        uint32_t a1 = *(const uint32_t*)&U[r1 * DLAT + ks + tg * 2];
        uint32_t a2 = *(const uint32_t*)&U[r0 * DLAT + ks + tg * 2 + 8];
        uint32_t a3 = *(const uint32_t*)&U[r1 * DLAT + ks + tg * 2 + 8];
        #pragma unroll
        for (int nf = 0; nf < 8; nf++) {
            int n = n0 + nf * 8 + gid;
            uint32_t b0 = *(const uint32_t*)&I[n * DLAT + ks + tg * 2];
            uint32_t b1 = *(const uint32_t*)&I[n * DLAT + ks + tg * 2 + 8];
            mma16816(c[nf], a0, a1, a2, a3, b0, b1);
        }
    }

    float bu0 = g_ubias[r0], bu1 = g_ubias[r1];
    #pragma unroll
    for (int nf = 0; nf < 8; nf++) {
        int col = n0 + nf * 8 + tg * 2;
        if (col < NUM_ITEMS) {   // col even, NUM_ITEMS even -> col+1 also in range
            float bi0 = bias_item[col], bi1 = bias_item[col + 1];
            float2 o0 = make_float2(sigf(c[nf][0] + bu0 + bi0), sigf(c[nf][1] + bu0 + bi1));
            float2 o1 = make_float2(sigf(c[nf][2] + bu1 + bi0), sigf(c[nf][3] + bu1 + bi1));
            *(float2*)&out[(size_t)r0 * NUM_ITEMS + col] = o0;
            *(float2*)&out[(size_t)r1 * NUM_ITEMS + col] = o1;
        }
    }
}

// ---------------- launch ----------------
extern "C" void kernel_launch(void* const* d_in, const int* in_sizes, int n_in,
                              void* d_out, int out_size) {
    const float* emb_user  = (const float*)d_in[0];
    const float* emb_item  = (const float*)d_in[1];
    const float* bias_user = (const float*)d_in[2];
    const float* bias_item = (const float*)d_in[3];
    const float* mm_user   = (const float*)d_in[4];
    const float* mm_item   = (const float*)d_in[5];
    const float* gvals     = (const float*)d_in[6];
    const int*   users     = (const int*)d_in[7];
    const int*   grows     = (const int*)d_in[8];
    const int*   gcols     = (const int*)d_in[9];
    float* out = (float*)d_out;

    const int T = 256;
    int nScanBlocks = (N_NODES + 1023) / 1024;   // 147

    // CSR build
    k_zero_cnt<<<(N_NODES + T - 1) / T, T>>>();
    k_hist<<<(NNZ_E + T - 1) / T, T>>>(grows);
    k_scanA<<<nScanBlocks, 1024>>>();
    k_scanB<<<1, 32>>>(nScanBlocks);
    k_scanC<<<(N_NODES + T - 1) / T, T>>>();
    k_scatter<<<(NNZ_E + T - 1) / T, T>>>(grows, gcols, gvals);

    // init fused embedding state
    k_init<<<(N_NODES * DTOT + T - 1) / T, T>>>(emb_user, emb_item, mm_user, mm_item);

    // 3 propagation layers (ping-pong x <-> y, acc accumulates)
    k_spmm<<<(N_NODES + 7) / 8, T>>>(0);   // x -> y
    k_spmm<<<(N_NODES + 7) / 8, T>>>(1);   // y -> x
    k_spmm<<<(N_NODES + 7) / 8, T>>>(0);   // x -> y

    // build bf16 user/item embeddings (with /4 and nearest-upsample folded in)
    int nBuild = NI_PAD * DLAT + NBATCH * DLAT;
    k_build<<<(nBuild + T - 1) / T, T>>>(users, bias_user);

    // rating = sigmoid(U @ I^T + biases)
    dim3 grid(NI_PAD / 128, NBATCH / 64);
    k_gemm<<<grid, 256>>>(bias_item, out);
}

// round 2
// speedup vs baseline: 1.1306x; 1.1306x over previous
#include <cuda_runtime.h>
#include <cuda_bf16.h>
#include <cstdint>

// Problem constants
#define NUM_USERS 50000
#define NUM_ITEMS 100000
#define N_NODES   150000
#define NNZ_E     2000000
#define DLAT      64
#define DMINI     16
#define DTOT      80           // fused 64 + 16
#define ROWU32    40           // DTOT/2 : bf16x2 words per node row
#define NBATCH    1024
#define NI_PAD    100096       // 782 * 128 (GEMM n-tile padding)

// ---------------- device scratch (allowed: __device__ globals) ----------------
__device__ int      g_rowptr[N_NODES + 1];
__device__ int      g_cnt[N_NODES];          // counts, then write cursors
__device__ int      g_bsum[256];
__device__ int2     g_cv[NNZ_E];             // {col*ROWU32, val bits}
__device__ uint32_t g_xu[N_NODES * ROWU32];  // bf16x2 state (ping)
__device__ uint32_t g_yu[N_NODES * ROWU32];  // bf16x2 state (pong)
__device__ float    g_acc[N_NODES * DTOT];   // fp32 accumulator
__device__ __nv_bfloat16 g_items[NI_PAD * DLAT];
__device__ __nv_bfloat16 g_users[NBATCH * DLAT];
__device__ float g_ubias[NBATCH];

// ---------------- CSR build ----------------
__global__ void k_zero_cnt() {
    int i = blockIdx.x * blockDim.x + threadIdx.x;
    if (i < N_NODES) g_cnt[i] = 0;
}

__global__ void k_hist(const int* __restrict__ rows) {
    int e = blockIdx.x * blockDim.x + threadIdx.x;
    if (e < NNZ_E) atomicAdd(&g_cnt[rows[e]], 1);
}

__global__ void k_scanA() {
    __shared__ int s[1024];
    int tid = threadIdx.x;
    int i = blockIdx.x * 1024 + tid;
    int v = (i < N_NODES) ? g_cnt[i] : 0;
    s[tid] = v;
    __syncthreads();
    #pragma unroll
    for (int off = 1; off < 1024; off <<= 1) {
        int t = (tid >= off) ? s[tid - off] : 0;
        __syncthreads();
        s[tid] += t;
        __syncthreads();
    }
    if (i < N_NODES) g_rowptr[i + 1] = s[tid];   // block-local inclusive
    if (tid == 1023) g_bsum[blockIdx.x] = s[1023];
}

// parallel exclusive scan over block sums (nb <= 256)
__global__ void k_scanB(int nb) {
    __shared__ int s[256];
    int t = threadIdx.x;
    int v = (t < nb) ? g_bsum[t] : 0;
    s[t] = v;
    __syncthreads();
    #pragma unroll
    for (int off = 1; off < 256; off <<= 1) {
        int u = (t >= off) ? s[t - off] : 0;
        __syncthreads();
        s[t] += u;
        __syncthreads();
    }
    if (t < nb) g_bsum[t] = s[t] - v;   // exclusive
}

__global__ void k_scanC() {
    int i = blockIdx.x * blockDim.x + threadIdx.x;
    if (i >= N_NODES) return;
    int incl = g_rowptr[i + 1] + g_bsum[i >> 10];
    g_rowptr[i + 1] = incl;
    int c = g_cnt[i];
    g_cnt[i] = incl - c;               // row start = write cursor
    if (i == 0) g_rowptr[0] = 0;
}

__global__ void k_scatter(const int* __restrict__ rows, const int* __restrict__ cols,
                          const float* __restrict__ vals) {
    int e = blockIdx.x * blockDim.x + threadIdx.x;
    if (e >= NNZ_E) return;
    int r = rows[e];
    int pos = atomicAdd(&g_cnt[r], 1);
    g_cv[pos] = make_int2(cols[e] * ROWU32, __float_as_int(vals[e]));
}

// ---------------- init fused 80-dim state (bf16 x + fp32 acc) ----------------
__global__ void k_init(const float* __restrict__ eu, const float* __restrict__ ei,
                       const float* __restrict__ mu, const float* __restrict__ mi) {
    int i = blockIdx.x * blockDim.x + threadIdx.x;   // over N_NODES*ROWU32
    if (i >= N_NODES * ROWU32) return;
    int n = i / ROWU32;
    int d2 = i - n * ROWU32;
    int d = 2 * d2;
    float v0, v1;
    if (d < DLAT) {
        const float* p = (n < NUM_USERS) ? (eu + n * DLAT) : (ei + (n - NUM_USERS) * DLAT);
        v0 = p[d]; v1 = p[d + 1];
    } else {
        int dd = d - DLAT;
        const float* p = (n < NUM_USERS) ? (mu + n * DMINI) : (mi + (n - NUM_USERS) * DMINI);
        v0 = p[dd]; v1 = p[dd + 1];
    }
    ((float2*)g_acc)[i] = make_float2(v0, v1);
    __nv_bfloat162 h = __floats2bfloat162_rn(v0, v1);
    g_xu[i] = *(uint32_t*)&h;
}

// ---------------- CSR SpMM (bf16 gather, fp32 accum): warp per row ----------------
__global__ void k_spmm(int dir) {
    const uint32_t* __restrict__ xu = dir ? g_yu : g_xu;
    uint32_t* __restrict__ yu       = dir ? g_xu : g_yu;
    int w = blockIdx.x * (blockDim.x >> 5) + (threadIdx.x >> 5);
    if (w >= N_NODES) return;
    int lane = threadIdx.x & 31;
    bool mini = lane < 8;
    int s = g_rowptr[w], e = g_rowptr[w + 1];

    float2 a0 = make_float2(0.f, 0.f);
    float2 a1 = make_float2(0.f, 0.f);

    int i = s;
    for (; i + 2 <= e; i += 2) {
        int2 cv0 = __ldg(&g_cv[i]);
        int2 cv1 = __ldg(&g_cv[i + 1]);
        uint32_t p0 = __ldg(&xu[cv0.x + lane]);
        uint32_t p1 = __ldg(&xu[cv1.x + lane]);
        uint32_t q0 = 0, q1 = 0;
        if (mini) {
            q0 = __ldg(&xu[cv0.x + 32 + lane]);
            q1 = __ldg(&xu[cv1.x + 32 + lane]);
        }
        float v0 = __int_as_float(cv0.y);
        float v1 = __int_as_float(cv1.y);
        float2 f;
        f = __bfloat1622float2(*(__nv_bfloat162*)&p0);
        a0.x = fmaf(v0, f.x, a0.x); a0.y = fmaf(v0, f.y, a0.y);
        f = __bfloat1622float2(*(__nv_bfloat162*)&p1);
        a0.x = fmaf(v1, f.x, a0.x); a0.y = fmaf(v1, f.y, a0.y);
        if (mini) {
            f = __bfloat1622float2(*(__nv_bfloat162*)&q0);
            a1.x = fmaf(v0, f.x, a1.x); a1.y = fmaf(v0, f.y, a1.y);
            f = __bfloat1622float2(*(__nv_bfloat162*)&q1);
            a1.x = fmaf(v1, f.x, a1.x); a1.y = fmaf(v1, f.y, a1.y);
        }
    }
    if (i < e) {
        int2 cv0 = __ldg(&g_cv[i]);
        uint32_t p0 = __ldg(&xu[cv0.x + lane]);
        uint32_t q0 = mini ? __ldg(&xu[cv0.x + 32 + lane]) : 0u;
        float v0 = __int_as_float(cv0.y);
        float2 f = __bfloat1622float2(*(__nv_bfloat162*)&p0);
        a0.x = fmaf(v0, f.x, a0.x); a0.y = fmaf(v0, f.y, a0.y);
        if (mini) {
            f = __bfloat1622float2(*(__nv_bfloat162*)&q0);
            a1.x = fmaf(v0, f.x, a1.x); a1.y = fmaf(v0, f.y, a1.y);
        }
    }

    int rb = w * ROWU32;
    __nv_bfloat162 h0 = __floats2bfloat162_rn(a0.x, a0.y);
    yu[rb + lane] = *(uint32_t*)&h0;
    float2* accp = (float2*)g_acc + rb + lane;
    float2 t = *accp; t.x += a0.x; t.y += a0.y; *accp = t;
    if (mini) {
        __nv_bfloat162 h1 = __floats2bfloat162_rn(a1.x, a1.y);
        yu[rb + 32 + lane] = *(uint32_t*)&h1;
        float2* accq = (float2*)g_acc + rb + 32 + lane;
        float2 u = *accq; u.x += a1.x; u.y += a1.y; *accq = u;
    }
}

// ---------------- build bf16 users/items embeddings (fold /4 + upsample) ----------------
__global__ void k_build(const int* __restrict__ users, const float* __restrict__ bias_user) {
    int idx = blockIdx.x * blockDim.x + threadIdx.x;
    const int NITEMS = NI_PAD * DLAT;
    if (idx < NITEMS) {
        int i = idx >> 6, d = idx & 63;
        float v = 0.f;
        if (i < NUM_ITEMS) {
            int node = NUM_USERS + i;
            v = 0.25f * (g_acc[node * DTOT + d] + g_acc[node * DTOT + 64 + (d >> 2)]);
        }
        g_items[idx] = __float2bfloat16(v);
    } else if (idx < NITEMS + NBATCH * DLAT) {
        int j = idx - NITEMS;
        int b = j >> 6, d = j & 63;
        int u = users[b];
        float v = 0.25f * (g_acc[u * DTOT + d] + g_acc[u * DTOT + 64 + (d >> 2)]);
        g_users[j] = __float2bfloat16(v);
        if (d == 0) g_ubias[b] = bias_user[u];
    }
}

// ---------------- rating GEMM: bf16 mma.sync + bias + sigmoid ----------------
__device__ __forceinline__ float sigf(float x) { return 1.0f / (1.0f + __expf(-x)); }

__device__ __forceinline__ void mma16816(float c[4], uint32_t a0, uint32_t a1,
                                         uint32_t a2, uint32_t a3,
                                         uint32_t b0, uint32_t b1) {
    asm volatile(
        "mma.sync.aligned.m16n8k16.row.col.f32.bf16.bf16.f32 "
        "{%0,%1,%2,%3},{%4,%5,%6,%7},{%8,%9},{%0,%1,%2,%3};\n"
        : "+f"(c[0]), "+f"(c[1]), "+f"(c[2]), "+f"(c[3])
        : "r"(a0), "r"(a1), "r"(a2), "r"(a3), "r"(b0), "r"(b1));
}

__global__ void k_gemm(const float* __restrict__ bias_item, float* __restrict__ out) {
    int warp = threadIdx.x >> 5, lane = threadIdx.x & 31;
    int gid = lane >> 2, tg = lane & 3;
    int m0 = blockIdx.y * 64 + (warp >> 1) * 16;   // 4 m-warps
    int n0 = blockIdx.x * 128 + (warp & 1) * 64;   // 2 n-warps

    float c[8][4];
    #pragma unroll
    for (int nf = 0; nf < 8; nf++)
        #pragma unroll
        for (int q = 0; q < 4; q++) c[nf][q] = 0.f;

    int r0 = m0 + gid, r1 = r0 + 8;
    const __nv_bfloat16* U = g_users;
    const __nv_bfloat16* I = g_items;

    #pragma unroll
    for (int ks = 0; ks < DLAT; ks += 16) {
        uint32_t a0 = *(const uint32_t*)&U[r0 * DLAT + ks + tg * 2];
        uint32_t a1 = *(const uint32_t*)&U[r1 * DLAT + ks + tg * 2];
        uint32_t a2 = *(const uint32_t*)&U[r0 * DLAT + ks + tg * 2 + 8];
        uint32_t a3 = *(const uint32_t*)&U[r1 * DLAT + ks + tg * 2 + 8];
        #pragma unroll
        for (int nf = 0; nf < 8; nf++) {
            int n = n0 + nf * 8 + gid;
            uint32_t b0 = *(const uint32_t*)&I[n * DLAT + ks + tg * 2];
            uint32_t b1 = *(const uint32_t*)&I[n * DLAT + ks + tg * 2 + 8];
            mma16816(c[nf], a0, a1, a2, a3, b0, b1);
        }
    }

    float bu0 = g_ubias[r0], bu1 = g_ubias[r1];
    #pragma unroll
    for (int nf = 0; nf < 8; nf++) {
        int col = n0 + nf * 8 + tg * 2;
        if (col < NUM_ITEMS) {   // col even, NUM_ITEMS even -> col+1 also in range
            float bi0 = bias_item[col], bi1 = bias_item[col + 1];
            float2 o0 = make_float2(sigf(c[nf][0] + bu0 + bi0), sigf(c[nf][1] + bu0 + bi1));
            float2 o1 = make_float2(sigf(c[nf][2] + bu1 + bi0), sigf(c[nf][3] + bu1 + bi1));
            *(float2*)&out[(size_t)r0 * NUM_ITEMS + col] = o0;
            *(float2*)&out[(size_t)r1 * NUM_ITEMS + col] = o1;
        }
    }
}

// ---------------- launch ----------------
extern "C" void kernel_launch(void* const* d_in, const int* in_sizes, int n_in,
                              void* d_out, int out_size) {
    const float* emb_user  = (const float*)d_in[0];
    const float* emb_item  = (const float*)d_in[1];
    const float* bias_user = (const float*)d_in[2];
    const float* bias_item = (const float*)d_in[3];
    const float* mm_user   = (const float*)d_in[4];
    const float* mm_item   = (const float*)d_in[5];
    const float* gvals     = (const float*)d_in[6];
    const int*   users     = (const int*)d_in[7];
    const int*   grows     = (const int*)d_in[8];
    const int*   gcols     = (const int*)d_in[9];
    float* out = (float*)d_out;

    const int T = 256;
    int nScanBlocks = (N_NODES + 1023) / 1024;   // 147

    // CSR build
    k_zero_cnt<<<(N_NODES + T - 1) / T, T>>>();
    k_hist<<<(NNZ_E + T - 1) / T, T>>>(grows);
    k_scanA<<<nScanBlocks, 1024>>>();
    k_scanB<<<1, 256>>>(nScanBlocks);
    k_scanC<<<(N_NODES + T - 1) / T, T>>>();
    k_scatter<<<(NNZ_E + T - 1) / T, T>>>(grows, gcols, gvals);

    // init fused embedding state
    k_init<<<(N_NODES * ROWU32 + T - 1) / T, T>>>(emb_user, emb_item, mm_user, mm_item);

    // 3 propagation layers (ping-pong x <-> y, acc accumulates)
    k_spmm<<<(N_NODES + 7) / 8, T>>>(0);   // x -> y
    k_spmm<<<(N_NODES + 7) / 8, T>>>(1);   // y -> x
    k_spmm<<<(N_NODES + 7) / 8, T>>>(0);   // x -> y

    // build bf16 user/item embeddings (with /4 and nearest-upsample folded in)
    int nBuild = NI_PAD * DLAT + NBATCH * DLAT;
    k_build<<<(nBuild + T - 1) / T, T>>>(users, bias_user);

    // rating = sigmoid(U @ I^T + biases)
    dim3 grid(NI_PAD / 128, NBATCH / 64);
    k_gemm<<<grid, 256>>>(bias_item, out);
}

// round 3
// speedup vs baseline: 1.2629x; 1.1170x over previous
#include <cuda_runtime.h>
#include <cuda_bf16.h>
#include <cstdint>

// Problem constants
#define NUM_USERS 50000
#define NUM_ITEMS 100000
#define N_NODES   150000
#define NNZ_E     2000000
#define DLAT      64
#define DMINI     16
#define DTOT      80           // fused 64 + 16
#define ROWPAD    64           // u32 words per node row (256B aligned; 40 used)
#define NSTR      (N_NODES * ROWPAD)
#define NBATCH    1024
#define NI_PAD    100096       // 782 * 128 (GEMM n-tile padding)

// ---------------- device scratch ----------------
__device__ int      g_rowptr[N_NODES + 1];
__device__ int      g_cnt[N_NODES];
__device__ int      g_bsum[256];
__device__ __align__(16) int2 g_cv[NNZ_E];   // {col*ROWPAD, val bits}
__device__ uint32_t g_buf[4 * NSTR];         // 4 bf16x2 layer buffers (A,B,C,D)
__device__ __nv_bfloat16 g_items[NI_PAD * DLAT];
__device__ __nv_bfloat16 g_users[NBATCH * DLAT];
__device__ float g_ubias[NBATCH];

// ---------------- CSR build ----------------
__global__ void k_zero_cnt() {
    int i = blockIdx.x * blockDim.x + threadIdx.x;
    if (i < N_NODES) g_cnt[i] = 0;
}

__global__ void k_hist(const int* __restrict__ rows) {
    int e = blockIdx.x * blockDim.x + threadIdx.x;
    if (e < NNZ_E) atomicAdd(&g_cnt[rows[e]], 1);
}

__global__ void k_scanA() {
    __shared__ int s[1024];
    int tid = threadIdx.x;
    int i = blockIdx.x * 1024 + tid;
    int v = (i < N_NODES) ? g_cnt[i] : 0;
    s[tid] = v;
    __syncthreads();
    #pragma unroll
    for (int off = 1; off < 1024; off <<= 1) {
        int t = (tid >= off) ? s[tid - off] : 0;
        __syncthreads();
        s[tid] += t;
        __syncthreads();
    }
    if (i < N_NODES) g_rowptr[i + 1] = s[tid];
    if (tid == 1023) g_bsum[blockIdx.x] = s[1023];
}

__global__ void k_scanB(int nb) {
    __shared__ int s[256];
    int t = threadIdx.x;
    int v = (t < nb) ? g_bsum[t] : 0;
    s[t] = v;
    __syncthreads();
    #pragma unroll
    for (int off = 1; off < 256; off <<= 1) {
        int u = (t >= off) ? s[t - off] : 0;
        __syncthreads();
        s[t] += u;
        __syncthreads();
    }
    if (t < nb) g_bsum[t] = s[t] - v;
}

__global__ void k_scanC() {
    int i = blockIdx.x * blockDim.x + threadIdx.x;
    if (i >= N_NODES) return;
    int incl = g_rowptr[i + 1] + g_bsum[i >> 10];
    g_rowptr[i + 1] = incl;
    int c = g_cnt[i];
    g_cnt[i] = incl - c;
    if (i == 0) g_rowptr[0] = 0;
}

__global__ void k_scatter(const int* __restrict__ rows, const int* __restrict__ cols,
                          const float* __restrict__ vals) {
    int e = blockIdx.x * blockDim.x + threadIdx.x;
    if (e >= NNZ_E) return;
    int r = rows[e];
    int pos = atomicAdd(&g_cnt[r], 1);
    g_cv[pos] = make_int2(cols[e] * ROWPAD, __float_as_int(vals[e]));
}

// ---------------- init buffer A (bf16, padded rows) ----------------
__global__ void k_init(const float* __restrict__ eu, const float* __restrict__ ei,
                       const float* __restrict__ mu, const float* __restrict__ mi) {
    int t = blockIdx.x * blockDim.x + threadIdx.x;   // over N_NODES*40
    if (t >= N_NODES * 40) return;
    int n = t / 40;
    int w = t - n * 40;
    int d = 2 * w;
    float v0, v1;
    if (d < DLAT) {
        const float* p = (n < NUM_USERS) ? (eu + n * DLAT) : (ei + (n - NUM_USERS) * DLAT);
        float2 f = *(const float2*)(p + d);
        v0 = f.x; v1 = f.y;
    } else {
        int dd = d - DLAT;
        const float* p = (n < NUM_USERS) ? (mu + n * DMINI) : (mi + (n - NUM_USERS) * DMINI);
        float2 f = *(const float2*)(p + dd);
        v0 = f.x; v1 = f.y;
    }
    __nv_bfloat162 h = __floats2bfloat162_rn(v0, v1);
    g_buf[n * ROWPAD + w] = *(uint32_t*)&h;
}

// ---------------- CSR SpMM: warp per row, 20 lanes x uint2, unroll 4 ----------------
__device__ __forceinline__ void edge_fma(uint2 g, float v, float4& a) {
    __nv_bfloat162 lo = *(__nv_bfloat162*)&g.x;
    __nv_bfloat162 hi = *(__nv_bfloat162*)&g.y;
    float2 f0 = __bfloat1622float2(lo);
    float2 f1 = __bfloat1622float2(hi);
    a.x = fmaf(v, f0.x, a.x);
    a.y = fmaf(v, f0.y, a.y);
    a.z = fmaf(v, f1.x, a.z);
    a.w = fmaf(v, f1.y, a.w);
}

__global__ void k_spmm(int src, int dst) {
    const uint32_t* __restrict__ xu = g_buf + (size_t)src * NSTR;
    uint32_t* __restrict__ yu       = g_buf + (size_t)dst * NSTR;
    int w = blockIdx.x * (blockDim.x >> 5) + (threadIdx.x >> 5);
    if (w >= N_NODES) return;
    int lane = threadIdx.x & 31;
    bool act = lane < 20;
    int s = g_rowptr[w], e = g_rowptr[w + 1];

    float4 a = make_float4(0.f, 0.f, 0.f, 0.f);

    int i = s;
    for (; i + 4 <= e; i += 4) {
        int2 cv0 = __ldg(&g_cv[i]);
        int2 cv1 = __ldg(&g_cv[i + 1]);
        int2 cv2 = __ldg(&g_cv[i + 2]);
        int2 cv3 = __ldg(&g_cv[i + 3]);
        uint2 g0, g1, g2, g3;
        if (act) {
            g0 = __ldg((const uint2*)(xu + cv0.x) + lane);
            g1 = __ldg((const uint2*)(xu + cv1.x) + lane);
            g2 = __ldg((const uint2*)(xu + cv2.x) + lane);
            g3 = __ldg((const uint2*)(xu + cv3.x) + lane);
            edge_fma(g0, __int_as_float(cv0.y), a);
            edge_fma(g1, __int_as_float(cv1.y), a);
            edge_fma(g2, __int_as_float(cv2.y), a);
            edge_fma(g3, __int_as_float(cv3.y), a);
        }
    }
    for (; i < e; i++) {
        int2 cv = __ldg(&g_cv[i]);
        if (act) {
            uint2 g = __ldg((const uint2*)(xu + cv.x) + lane);
            edge_fma(g, __int_as_float(cv.y), a);
        }
    }

    if (act) {
        __nv_bfloat162 h0 = __floats2bfloat162_rn(a.x, a.y);
        __nv_bfloat162 h1 = __floats2bfloat162_rn(a.z, a.w);
        uint2 o = make_uint2(*(uint32_t*)&h0, *(uint32_t*)&h1);
        ((uint2*)(yu + w * ROWPAD))[lane] = o;
    }
}

// ---------------- build bf16 users/items (sum 4 layers, /4, upsample) ----------------
// one thread handles 4 consecutive output dims [4q, 4q+4), q in 0..15
__device__ __forceinline__ void build4(int node, int q, __nv_bfloat16* dst) {
    float s0 = 0.f, s1 = 0.f, s2 = 0.f, s3 = 0.f, mini = 0.f;
    #pragma unroll
    for (int b = 0; b < 4; b++) {
        const uint32_t* row = g_buf + (size_t)b * NSTR + node * ROWPAD;
        uint2 wv = *(const uint2*)(row + 2 * q);
        float2 f0 = __bfloat1622float2(*(__nv_bfloat162*)&wv.x);
        float2 f1 = __bfloat1622float2(*(__nv_bfloat162*)&wv.y);
        s0 += f0.x; s1 += f0.y; s2 += f1.x; s3 += f1.y;
        uint32_t mw = row[32 + (q >> 1)];
        __nv_bfloat162 mh = *(__nv_bfloat162*)&mw;
        float2 mf = __bfloat1622float2(mh);
        mini += (q & 1) ? mf.y : mf.x;
    }
    __nv_bfloat162 o0 = __floats2bfloat162_rn(0.25f * (s0 + mini), 0.25f * (s1 + mini));
    __nv_bfloat162 o1 = __floats2bfloat162_rn(0.25f * (s2 + mini), 0.25f * (s3 + mini));
    uint2 o = make_uint2(*(uint32_t*)&o0, *(uint32_t*)&o1);
    *(uint2*)dst = o;
}

__global__ void k_build(const int* __restrict__ users, const float* __restrict__ bias_user) {
    int idx = blockIdx.x * blockDim.x + threadIdx.x;
    const int NIT = NI_PAD * 16;
    if (idx < NIT) {
        int i = idx >> 4, q = idx & 15;
        if (i < NUM_ITEMS) {
            build4(NUM_USERS + i, q, g_items + i * DLAT + 4 * q);
        } else {
            *(uint2*)(g_items + i * DLAT + 4 * q) = make_uint2(0u, 0u);
        }
    } else if (idx < NIT + NBATCH * 16) {
        int j = idx - NIT;
        int b = j >> 4, q = j & 15;
        int u = users[b];
        build4(u, q, g_users + b * DLAT + 4 * q);
        if (q == 0) g_ubias[b] = bias_user[u];
    }
}

// ---------------- rating GEMM: bf16 mma.sync + bias + sigmoid ----------------
__device__ __forceinline__ float sigf(float x) { return 1.0f / (1.0f + __expf(-x)); }

__device__ __forceinline__ void mma16816(float c[4], uint32_t a0, uint32_t a1,
                                         uint32_t a2, uint32_t a3,
                                         uint32_t b0, uint32_t b1) {
    asm volatile(
        "mma.sync.aligned.m16n8k16.row.col.f32.bf16.bf16.f32 "
        "{%0,%1,%2,%3},{%4,%5,%6,%7},{%8,%9},{%0,%1,%2,%3};\n"
        : "+f"(c[0]), "+f"(c[1]), "+f"(c[2]), "+f"(c[3])
        : "r"(a0), "r"(a1), "r"(a2), "r"(a3), "r"(b0), "r"(b1));
}

__global__ void k_gemm(const float* __restrict__ bias_item, float* __restrict__ out) {
    int warp = threadIdx.x >> 5, lane = threadIdx.x & 31;
    int gid = lane >> 2, tg = lane & 3;
    int m0 = blockIdx.y * 64 + (warp >> 1) * 16;
    int n0 = blockIdx.x * 128 + (warp & 1) * 64;

    float c[8][4];
    #pragma unroll
    for (int nf = 0; nf < 8; nf++)
        #pragma unroll
        for (int q = 0; q < 4; q++) c[nf][q] = 0.f;

    int r0 = m0 + gid, r1 = r0 + 8;
    const __nv_bfloat16* U = g_users;
    const __nv_bfloat16* I = g_items;

    #pragma unroll
    for (int ks = 0; ks < DLAT; ks += 16) {
        uint32_t a0 = *(const uint32_t*)&U[r0 * DLAT + ks + tg * 2];
        uint32_t a1 = *(const uint32_t*)&U[r1 * DLAT + ks + tg * 2];
        uint32_t a2 = *(const uint32_t*)&U[r0 * DLAT + ks + tg * 2 + 8];
        uint32_t a3 = *(const uint32_t*)&U[r1 * DLAT + ks + tg * 2 + 8];
        #pragma unroll
        for (int nf = 0; nf < 8; nf++) {
            int n = n0 + nf * 8 + gid;
            uint32_t b0 = *(const uint32_t*)&I[n * DLAT + ks + tg * 2];
            uint32_t b1 = *(const uint32_t*)&I[n * DLAT + ks + tg * 2 + 8];
            mma16816(c[nf], a0, a1, a2, a3, b0, b1);
        }
    }

    float bu0 = g_ubias[r0], bu1 = g_ubias[r1];
    #pragma unroll
    for (int nf = 0; nf < 8; nf++) {
        int col = n0 + nf * 8 + tg * 2;
        if (col < NUM_ITEMS) {
            float bi0 = bias_item[col], bi1 = bias_item[col + 1];
            float2 o0 = make_float2(sigf(c[nf][0] + bu0 + bi0), sigf(c[nf][1] + bu0 + bi1));
            float2 o1 = make_float2(sigf(c[nf][2] + bu1 + bi0), sigf(c[nf][3] + bu1 + bi1));
            *(float2*)&out[(size_t)r0 * NUM_ITEMS + col] = o0;
            *(float2*)&out[(size_t)r1 * NUM_ITEMS + col] = o1;
        }
    }
}

// ---------------- launch ----------------
extern "C" void kernel_launch(void* const* d_in, const int* in_sizes, int n_in,
                              void* d_out, int out_size) {
    const float* emb_user  = (const float*)d_in[0];
    const float* emb_item  = (const float*)d_in[1];
    const float* bias_user = (const float*)d_in[2];
    const float* bias_item = (const float*)d_in[3];
    const float* mm_user   = (const float*)d_in[4];
    const float* mm_item   = (const float*)d_in[5];
    const float* gvals     = (const float*)d_in[6];
    const int*   users     = (const int*)d_in[7];
    const int*   grows     = (const int*)d_in[8];
    const int*   gcols     = (const int*)d_in[9];
    float* out = (float*)d_out;

    const int T = 256;
    int nScanBlocks = (N_NODES + 1023) / 1024;   // 147

    // CSR build
    k_zero_cnt<<<(N_NODES + T - 1) / T, T>>>();
    k_hist<<<(NNZ_E + T - 1) / T, T>>>(grows);
    k_scanA<<<nScanBlocks, 1024>>>();
    k_scanB<<<1, 256>>>(nScanBlocks);
    k_scanC<<<(N_NODES + T - 1) / T, T>>>();
    k_scatter<<<(NNZ_E + T - 1) / T, T>>>(grows, gcols, gvals);

    // init buffer A
    k_init<<<(N_NODES * 40 + T - 1) / T, T>>>(emb_user, emb_item, mm_user, mm_item);

    // 3 propagation layers: A->B->C->D
    k_spmm<<<(N_NODES + 7) / 8, T>>>(0, 1);
    k_spmm<<<(N_NODES + 7) / 8, T>>>(1, 2);
    k_spmm<<<(N_NODES + 7) / 8, T>>>(2, 3);

    // build bf16 user/item embeddings
    int nBuild = NI_PAD * 16 + NBATCH * 16;
    k_build<<<(nBuild + T - 1) / T, T>>>(users, bias_user);

    // rating = sigmoid(U @ I^T + biases)
    dim3 grid(NI_PAD / 128, NBATCH / 64);
    k_gemm<<<grid, 256>>>(bias_item, out);
}